// round 15
// baseline (speedup 1.0000x reference)
#include <cuda_runtime.h>
#include <math.h>

#define L_SEQ 4096
#define B_SZ  64
#define C_IN  256
#define H_SZ  256
#define WPAD  260   // padded smem row stride (floats): 1040B, 16B-aligned

// ---- packed fp32x2 helpers (phase 1 only; each lane is IEEE rn fp32 fma) ----
__device__ __forceinline__ unsigned long long fma2(unsigned long long a,
                                                   unsigned long long b,
                                                   unsigned long long c) {
    unsigned long long d;
    asm("fma.rn.f32x2 %0, %1, %2, %3;" : "=l"(d) : "l"(a), "l"(b), "l"(c));
    return d;
}
__device__ __forceinline__ unsigned long long dup2(float a) {
    unsigned long long d;
    asm("mov.b64 %0, {%1, %1};" : "=l"(d) : "f"(a));
    return d;
}
__device__ __forceinline__ void unpack2(unsigned long long v, float& lo, float& hi) {
    asm("mov.b64 {%0, %1}, %2;" : "=f"(lo), "=f"(hi) : "l"(v));
}
__device__ __forceinline__ unsigned smem_u32(const void* p) {
    unsigned r;
    asm("{ .reg .u64 t; cvta.to.shared.u64 t, %1; cvt.u32.u64 %0, t; }" : "=r"(r) : "l"(p));
    return r;
}
__device__ __forceinline__ unsigned mapa_u32(unsigned local_addr, unsigned peer) {
    unsigned r;
    asm("mapa.shared::cluster.u32 %0, %1, %2;" : "=r"(r) : "r"(local_addr), "r"(peer));
    return r;
}
__device__ __forceinline__ void mbar_wait_acq_cluster(unsigned addr, unsigned parity) {
    asm volatile(
        "{\n\t.reg .pred P;\n\t"
        "WL%=:\n\t"
        "mbarrier.try_wait.parity.acquire.cluster.shared::cta.b64 P, [%0], %1, 0x989680;\n\t"
        "@P bra WD%=;\n\t"
        "bra WL%=;\n\t"
        "WD%=:\n\t}"
        :: "r"(addr), "r"(parity) : "memory");
}

// ---- XLA:CPU EmitFastTanh, with_fma=true path (Eigen generic_fast_tanh_float,
// EIGEN_VECTORIZE_FMA): clamp +-7.99881172180175781, fused-FMA Horner, rn div,
// |x| < 0.0004 passthrough of the UNCLAMPED input. ----
__device__ __forceinline__ float xla_tanh(float x) {
    const float kClamp = 7.99881172180175781f;
    float xc = fminf(fmaxf(x, -kClamp), kClamp);
    float x2 = __fmul_rn(xc, xc);
    float p  = __fmaf_rn(x2, -2.76076847742355e-16f, 2.00018790482477e-13f);
    p = __fmaf_rn(x2, p, -8.60467152213735e-11f);
    p = __fmaf_rn(x2, p,  5.12229709037114e-08f);
    p = __fmaf_rn(x2, p,  1.48572235717979e-05f);
    p = __fmaf_rn(x2, p,  6.37261928875436e-04f);
    p = __fmaf_rn(x2, p,  4.89352455891786e-03f);
    p = __fmul_rn(xc, p);
    float q  = __fmaf_rn(x2, 1.19825839466702e-06f, 1.18534705686654e-04f);
    q = __fmaf_rn(x2, q, 2.26843463243900e-03f);
    q = __fmaf_rn(x2, q, 4.89352518554385e-03f);
    float r = __fdiv_rn(p, q);
    return (fabsf(x) < 0.0004f) ? x : r;
}

// ---------------------------------------------------------------------------
// Phase 1: out[m,n] = (sum_{k=0..255 ascending, single acc} X[m,k]*W_ih[n,k]) + b[n]
// Matches Eigen gebp reduction order (single accumulator per output, k ascending).
// ---------------------------------------------------------------------------
__global__ void __launch_bounds__(256, 2)
rnn_xproj(const float* __restrict__ X, const float* __restrict__ W,
          const float* __restrict__ bias, float* __restrict__ out)
{
    __shared__ __align__(16) float As[16][128];
    __shared__ __align__(16) float Bs[16][128];

    const int t  = threadIdx.x;
    const int m0 = (blockIdx.x >> 1) * 128;
    const int n0 = (blockIdx.x & 1) * 128;
    const int tn = t & 15, tm = t >> 4;

    unsigned long long acc[8][4];
#pragma unroll
    for (int i = 0; i < 8; i++)
#pragma unroll
        for (int j = 0; j < 4; j++) acc[i][j] = 0ULL;

    const float* Xb = X + (long long)m0 * C_IN;
    const float* Wb = W + (long long)n0 * C_IN;

    for (int ic = 0; ic < 16; ic++) {
        const int kc = ic * 16;
        __syncthreads();
#pragma unroll
        for (int q = 0; q < 2; q++) {
            int f = t + q * 256;
            int row = f >> 2, c4 = f & 3;
            float4 xv = *reinterpret_cast<const float4*>(Xb + row * C_IN + kc + c4 * 4);
            float4 wv = *reinterpret_cast<const float4*>(Wb + row * C_IN + kc + c4 * 4);
            As[c4 * 4 + 0][row] = xv.x; As[c4 * 4 + 1][row] = xv.y;
            As[c4 * 4 + 2][row] = xv.z; As[c4 * 4 + 3][row] = xv.w;
            Bs[c4 * 4 + 0][row] = wv.x; Bs[c4 * 4 + 1][row] = wv.y;
            Bs[c4 * 4 + 2][row] = wv.z; Bs[c4 * 4 + 3][row] = wv.w;
        }
        __syncthreads();
#pragma unroll
        for (int kk = 0; kk < 16; kk++) {
            float4 aA = *reinterpret_cast<const float4*>(&As[kk][tm * 8]);
            float4 aB = *reinterpret_cast<const float4*>(&As[kk][tm * 8 + 4]);
            ulonglong2 b01 = *reinterpret_cast<const ulonglong2*>(&Bs[kk][tn * 8]);
            ulonglong2 b23 = *reinterpret_cast<const ulonglong2*>(&Bs[kk][tn * 8 + 4]);
            unsigned long long ad[8];
            ad[0] = dup2(aA.x); ad[1] = dup2(aA.y); ad[2] = dup2(aA.z); ad[3] = dup2(aA.w);
            ad[4] = dup2(aB.x); ad[5] = dup2(aB.y); ad[6] = dup2(aB.z); ad[7] = dup2(aB.w);
#pragma unroll
            for (int mi = 0; mi < 8; mi++) {
                acc[mi][0] = fma2(ad[mi], b01.x, acc[mi][0]);
                acc[mi][1] = fma2(ad[mi], b01.y, acc[mi][1]);
                acc[mi][2] = fma2(ad[mi], b23.x, acc[mi][2]);
                acc[mi][3] = fma2(ad[mi], b23.y, acc[mi][3]);
            }
        }
    }

    float4 bv0 = *reinterpret_cast<const float4*>(bias + n0 + tn * 8);
    float4 bv1 = *reinterpret_cast<const float4*>(bias + n0 + tn * 8 + 4);
#pragma unroll
    for (int mi = 0; mi < 8; mi++) {
        long long m = m0 + tm * 8 + mi;
        float4 o0, o1;
        unpack2(acc[mi][0], o0.x, o0.y);
        unpack2(acc[mi][1], o0.z, o0.w);
        unpack2(acc[mi][2], o1.x, o1.y);
        unpack2(acc[mi][3], o1.z, o1.w);
        o0.x = __fadd_rn(o0.x, bv0.x); o0.y = __fadd_rn(o0.y, bv0.y);
        o0.z = __fadd_rn(o0.z, bv0.z); o0.w = __fadd_rn(o0.w, bv0.w);
        o1.x = __fadd_rn(o1.x, bv1.x); o1.y = __fadd_rn(o1.y, bv1.y);
        o1.z = __fadd_rn(o1.z, bv1.z); o1.w = __fadd_rn(o1.w, bv1.w);
        *reinterpret_cast<float4*>(out + m * H_SZ + n0 + tn * 8)     = o0;
        *reinterpret_cast<float4*>(out + m * H_SZ + n0 + tn * 8 + 4) = o1;
    }
}

// ---------------------------------------------------------------------------
// Phase 2: recurrence, bit-exact summation order (single acc, k ascending).
// 2-CTA cluster per batch element; each CTA holds its 128-row half of W_hh in
// padded smem. Thread t owns output row jglob = rank*128 + t.
// New h exchanged across the cluster via st.shared::cluster + double-buffered
// 256-count mbarriers (128 local + 128 remote arrivals per phase).
// ---------------------------------------------------------------------------
__global__ void __launch_bounds__(128, 1) __cluster_dims__(2, 1, 1)
rnn_recur(float* out, const float* __restrict__ h0, const float* __restrict__ W_hh)
{
    extern __shared__ __align__(16) float Ws[];          // [128][WPAD]
    __shared__ __align__(16) float hbuf[2][H_SZ];
    __shared__ __align__(8) unsigned long long mbar[2];

    const int t = threadIdx.x;                           // 0..127
    unsigned rank;
    asm("mov.u32 %0, %%cluster_ctarank;" : "=r"(rank));
    const int b     = blockIdx.x >> 1;
    const int jglob = (int)rank * 128 + t;

    for (int idx = t; idx < 128 * H_SZ; idx += 128) {
        int r = idx >> 8, c = idx & 255;
        Ws[r * WPAD + c] = W_hh[((int)rank * 128 + r) * H_SZ + c];
    }
    hbuf[0][t]       = h0[b * H_SZ + t];
    hbuf[0][t + 128] = h0[b * H_SZ + t + 128];
    if (t == 0) {
        unsigned cnt = 256;
        asm volatile("mbarrier.init.shared.b64 [%0], %1;" :: "r"(smem_u32(&mbar[0])), "r"(cnt) : "memory");
        asm volatile("mbarrier.init.shared.b64 [%0], %1;" :: "r"(smem_u32(&mbar[1])), "r"(cnt) : "memory");
    }
    __syncthreads();
    asm volatile("barrier.cluster.arrive.aligned;" ::: "memory");
    asm volatile("barrier.cluster.wait.aligned;"   ::: "memory");

    const unsigned peer = rank ^ 1u;
    unsigned loc_h[2], rem_h[2], loc_bar[2], rem_bar[2];
#pragma unroll
    for (int i = 0; i < 2; i++) {
        loc_h[i]   = smem_u32(&hbuf[i][jglob]);
        rem_h[i]   = mapa_u32(loc_h[i], peer);
        loc_bar[i] = smem_u32(&mbar[i]);
        rem_bar[i] = mapa_u32(loc_bar[i], peer);
    }

    const float4* wr = reinterpret_cast<const float4*>(Ws + t * WPAD);
    float xw_next = out[(0 * B_SZ + b) * H_SZ + jglob];

    for (int l = 0; l < L_SEQ; l++) {
        const int cur = l & 1;
        const int nxt = cur ^ 1;
        const unsigned parity = (unsigned)((l >> 1) & 1);
        float xw_cur = xw_next;
        if (l + 1 < L_SEQ)
            xw_next = out[((l + 1) * B_SZ + b) * H_SZ + jglob];

        // Strictly ascending-k serial FMA chain, single accumulator from 0.0f.
        const float4* hr = reinterpret_cast<const float4*>(&hbuf[cur][0]);
        float acc = 0.0f;
#pragma unroll
        for (int k4 = 0; k4 < 64; k4++) {
            float4 wv = wr[k4];
            float4 hv = hr[k4];
            acc = __fmaf_rn(wv.x, hv.x, acc);
            acc = __fmaf_rn(wv.y, hv.y, acc);
            acc = __fmaf_rn(wv.z, hv.z, acc);
            acc = __fmaf_rn(wv.w, hv.w, acc);
        }

        float z = __fadd_rn(xw_cur, acc);
        float h = xla_tanh(z);
        out[((long long)l * B_SZ + b) * H_SZ + jglob] = h;   // outputs[l]

        if (l + 1 < L_SEQ) {
            asm volatile("st.shared.f32 [%0], %1;" :: "r"(loc_h[nxt]), "f"(h) : "memory");
            asm volatile("st.shared::cluster.f32 [%0], %1;" :: "r"(rem_h[nxt]), "f"(h) : "memory");
            asm volatile("mbarrier.arrive.release.cluster.shared::cluster.b64 _, [%0];"
                         :: "r"(rem_bar[nxt]) : "memory");
            asm volatile("mbarrier.arrive.release.cluster.shared::cta.b64 _, [%0];"
                         :: "r"(loc_bar[nxt]) : "memory");
            mbar_wait_acq_cluster(loc_bar[nxt], parity);
        } else {
            out[(long long)L_SEQ * B_SZ * H_SZ + b * H_SZ + jglob] = h;  // h_last
        }
    }

    asm volatile("barrier.cluster.arrive.aligned;" ::: "memory");
    asm volatile("barrier.cluster.wait.aligned;"   ::: "memory");
}

extern "C" void kernel_launch(void* const* d_in, const int* in_sizes, int n_in,
                              void* d_out, int out_size) {
    const float* x    = (const float*)d_in[0];
    const float* h0   = (const float*)d_in[1];
    const float* W_ih = (const float*)d_in[2];
    const float* W_hh = (const float*)d_in[3];
    const float* bias = (const float*)d_in[4];
    float* out = (float*)d_out;

    static int smem_set = 0;
    const int dyn_smem = 128 * WPAD * sizeof(float);     // 133120 B
    if (!smem_set) {
        cudaFuncSetAttribute(rnn_recur, cudaFuncAttributeMaxDynamicSharedMemorySize, dyn_smem);
        smem_set = 1;
    }

    // Phase 1: xW + b into the outputs region of d_out.
    rnn_xproj<<<(L_SEQ * B_SZ / 128) * 2, 256>>>(x, W_ih, bias, out);
    // Phase 2: sequential recurrence (bit-exact order), in-place over outputs.
    rnn_recur<<<2 * B_SZ, 128, dyn_smem>>>(out, h0, W_hh);
}